// round 3
// baseline (speedup 1.0000x reference)
#include <cuda_runtime.h>
#include <math.h>
#include <stdint.h>

// Problem constants: G=1, E=8, C=2048, H=1024, I=4096
#define EXPERTS 8
#define CDIM 2048
#define HDIM 1024
#define IDIM 4096

#define BM 128
#define BN 128
#define BK 32

// Hidden scratch: E * C * I fp32 = 256 MB, as a __device__ global
// (allocation inside kernel_launch is forbidden; device globals are the
// sanctioned workaround).
__device__ float g_hidden[(size_t)EXPERTS * CDIM * IDIM];

__device__ __forceinline__ float tf32f(float x) {
    // Round-to-nearest TF32 (value stays in a float register; mma reads bits)
    float y;
    asm("cvt.rna.tf32.f32 %0, %1;" : "=f"(y) : "f"(x));
    return y;
}

__device__ __forceinline__ float gelu_exact(float x) {
    return 0.5f * x * (1.0f + erff(x * 0.70710678118654752440f));
}

// D[M,N] = act(A[M,K] @ B[K,N]) per expert (blockIdx.z).
// A, B, D are per-expert contiguous row-major, strides e*M*K / e*K*N / e*M*N.
// Requires M%128==0, N%128==0, K%32==0 (true for all calls here).
template <bool GELU>
__global__ void __launch_bounds__(256)
gemm_tf32_kernel(const float* __restrict__ A,
                 const float* __restrict__ B,
                 float* __restrict__ D,
                 int M, int N, int K)
{
    const int e = blockIdx.z;
    A += (size_t)e * M * K;
    B += (size_t)e * K * N;
    D += (size_t)e * M * N;

    __shared__ float As[BK][BM + 4];   // [k][m], row stride 132 floats
    __shared__ float Bs[BK][BN + 4];   // [k][n], row stride 132 floats

    const int tid  = threadIdx.x;
    const int lane = tid & 31;
    const int warp = tid >> 5;

    const int m0 = blockIdx.y * BM;
    const int n0 = blockIdx.x * BN;

    // Warp tiling: 2 warps along M (64 rows each), 4 along N (32 cols each)
    const int wm = (warp & 1) * 64;
    const int wn = (warp >> 1) * 32;

    // Global->smem staging mapping
    const int a_c4 = tid & 7;        // which float4 along K (8 per row)
    const int a_r  = tid >> 3;       // row 0..31, +32*it
    const int b_c4 = tid & 31;       // which float4 along N (32 per row)
    const int b_r  = tid >> 5;       // row 0..7, +8*it

    const int q = lane & 3;          // k sub-index within mma fragment
    const int r = lane >> 2;         // row/col sub-index within fragment

    float acc[4][4][4];
    #pragma unroll
    for (int i = 0; i < 4; i++)
        #pragma unroll
        for (int j = 0; j < 4; j++)
            #pragma unroll
            for (int v = 0; v < 4; v++)
                acc[i][j][v] = 0.0f;

    for (int k0 = 0; k0 < K; k0 += BK) {
        // Stage global loads in registers before syncing
        float4 av[4], bv[4];
        #pragma unroll
        for (int it = 0; it < 4; it++)
            av[it] = *reinterpret_cast<const float4*>(
                &A[(size_t)(m0 + a_r + 32 * it) * K + k0 + 4 * a_c4]);
        #pragma unroll
        for (int it = 0; it < 4; it++)
            bv[it] = *reinterpret_cast<const float4*>(
                &B[(size_t)(k0 + b_r + 8 * it) * N + n0 + 4 * b_c4]);

        __syncthreads();  // previous tile's compute done

        // A: store transposed [k][m], converting to tf32 once here
        #pragma unroll
        for (int it = 0; it < 4; it++) {
            As[4 * a_c4 + 0][a_r + 32 * it] = tf32f(av[it].x);
            As[4 * a_c4 + 1][a_r + 32 * it] = tf32f(av[it].y);
            As[4 * a_c4 + 2][a_r + 32 * it] = tf32f(av[it].z);
            As[4 * a_c4 + 3][a_r + 32 * it] = tf32f(av[it].w);
        }
        // B: store [k][n] vectorized
        #pragma unroll
        for (int it = 0; it < 4; it++) {
            float4 t = bv[it];
            t.x = tf32f(t.x); t.y = tf32f(t.y);
            t.z = tf32f(t.z); t.w = tf32f(t.w);
            *reinterpret_cast<float4*>(&Bs[b_r + 8 * it][4 * b_c4]) = t;
        }

        __syncthreads();

        // 4 k-steps of k=8 per 32-deep tile
        #pragma unroll
        for (int kk = 0; kk < 4; kk++) {
            const int kb = kk * 8;

            unsigned af[4][4];
            #pragma unroll
            for (int mf = 0; mf < 4; mf++) {
                const int mr = wm + mf * 16 + r;
                af[mf][0] = __float_as_uint(As[kb + q    ][mr    ]);
                af[mf][1] = __float_as_uint(As[kb + q    ][mr + 8]);
                af[mf][2] = __float_as_uint(As[kb + q + 4][mr    ]);
                af[mf][3] = __float_as_uint(As[kb + q + 4][mr + 8]);
            }
            unsigned bf[4][2];
            #pragma unroll
            for (int nf = 0; nf < 4; nf++) {
                const int nc = wn + nf * 8 + r;
                bf[nf][0] = __float_as_uint(Bs[kb + q    ][nc]);
                bf[nf][1] = __float_as_uint(Bs[kb + q + 4][nc]);
            }

            #pragma unroll
            for (int mf = 0; mf < 4; mf++)
                #pragma unroll
                for (int nf = 0; nf < 4; nf++) {
                    asm volatile(
                        "mma.sync.aligned.m16n8k8.row.col.f32.tf32.tf32.f32 "
                        "{%0,%1,%2,%3}, {%4,%5,%6,%7}, {%8,%9}, {%0,%1,%2,%3};\n"
                        : "+f"(acc[mf][nf][0]), "+f"(acc[mf][nf][1]),
                          "+f"(acc[mf][nf][2]), "+f"(acc[mf][nf][3])
                        : "r"(af[mf][0]), "r"(af[mf][1]),
                          "r"(af[mf][2]), "r"(af[mf][3]),
                          "r"(bf[nf][0]), "r"(bf[nf][1]));
                }
        }
    }

    // Epilogue: fragment (row, col) mapping for m16n8k8 C tile
    #pragma unroll
    for (int mf = 0; mf < 4; mf++) {
        #pragma unroll
        for (int nf = 0; nf < 4; nf++) {
            const int row = m0 + wm + mf * 16 + r;
            const int col = n0 + wn + nf * 8 + 2 * q;
            float v0 = acc[mf][nf][0];
            float v1 = acc[mf][nf][1];
            float v2 = acc[mf][nf][2];
            float v3 = acc[mf][nf][3];
            if (GELU) {
                v0 = gelu_exact(v0); v1 = gelu_exact(v1);
                v2 = gelu_exact(v2); v3 = gelu_exact(v3);
            }
            float2 p0 = make_float2(v0, v1);
            float2 p1 = make_float2(v2, v3);
            *reinterpret_cast<float2*>(&D[(size_t)row * N + col])       = p0;
            *reinterpret_cast<float2*>(&D[(size_t)(row + 8) * N + col]) = p1;
        }
    }
}

extern "C" void kernel_launch(void* const* d_in, const int* in_sizes, int n_in,
                              void* d_out, int out_size) {
    (void)in_sizes; (void)n_in; (void)out_size;
    const float* x  = (const float*)d_in[0];  // [1,8,2048,1024] == [E,C,H]
    const float* wi = (const float*)d_in[1];  // [E,1024,4096]
    const float* wo = (const float*)d_in[2];  // [E,4096,1024]
    float* out = (float*)d_out;               // [E,2048,1024]

    float* hidden = nullptr;
    cudaGetSymbolAddress((void**)&hidden, g_hidden);

    dim3 block(256);
    // GEMM1 + GELU: [2048,1024] @ [1024,4096] -> hidden [2048,4096]
    dim3 grid1(IDIM / BN, CDIM / BM, EXPERTS);
    gemm_tf32_kernel<true><<<grid1, block>>>(x, wi, hidden, CDIM, IDIM, HDIM);
    // GEMM2: hidden [2048,4096] @ [4096,1024] -> out [2048,1024]
    dim3 grid2(HDIM / BN, CDIM / BM, EXPERTS);
    gemm_tf32_kernel<false><<<grid2, block>>>(hidden, wo, out, CDIM, HDIM, IDIM);
}

// round 5
// speedup vs baseline: 1.3572x; 1.3572x over previous
#include <cuda_runtime.h>
#include <math.h>
#include <stdint.h>

// Problem: G=1, E=8, C=2048, H=1024, I=4096
#define EXPERTS 8
#define CDIM 2048
#define HDIM 1024
#define IDIM 4096

#define BM 128
#define BN 256
#define BK 32
#define NTHREADS 256
#define NSTAGES 3

// smem: rows padded to 36 floats (144B) -> fragment bank = 4r+q, conflict-free
#define ROWF 36
#define A_STAGE_BYTES (BM * ROWF * 4)            // 18432
#define B_STAGE_BYTES (BN * ROWF * 4)            // 36864
#define STAGE_BYTES   (A_STAGE_BYTES + B_STAGE_BYTES)  // 55296
#define SMEM_TOTAL    (NSTAGES * STAGE_BYTES)    // 165888

// Scratch (device globals; allocation APIs forbidden)
__device__ float g_hidden[(size_t)EXPERTS * CDIM * IDIM];  // 256 MB
__device__ float g_xr[(size_t)EXPERTS * CDIM * HDIM];      // 64 MB (tf32-rounded x)
__device__ float g_wiT[(size_t)EXPERTS * HDIM * IDIM];     // 128 MB [E][I][H]
__device__ float g_woT[(size_t)EXPERTS * HDIM * IDIM];     // 128 MB [E][H][I]

__device__ __forceinline__ float tf32f(float x) {
    float y;
    asm("cvt.rna.tf32.f32 %0, %1;" : "=f"(y) : "f"(x));
    return y;
}
__device__ __forceinline__ float gelu_exact(float x) {
    return 0.5f * x * (1.0f + erff(x * 0.70710678118654752440f));
}
__device__ __forceinline__ uint32_t smem_u32(const void* p) {
    uint32_t a;
    asm("{ .reg .u64 t; cvta.to.shared.u64 t, %1; cvt.u32.u64 %0, t; }" : "=r"(a) : "l"(p));
    return a;
}
__device__ __forceinline__ void cp_async16(uint32_t dst, const void* src) {
    asm volatile("cp.async.cg.shared.global [%0], [%1], 16;"
                 :: "r"(dst), "l"(src) : "memory");
}
__device__ __forceinline__ void cp_commit() {
    asm volatile("cp.async.commit_group;" ::: "memory");
}
__device__ __forceinline__ void cp_wait1() {
    asm volatile("cp.async.wait_group 1;" ::: "memory");
}

// ---------------- elementwise tf32 round ----------------
__global__ void __launch_bounds__(256)
round_tf32(const float* __restrict__ in, float* __restrict__ out, size_t n)
{
    size_t i = (size_t)blockIdx.x * 1024 + threadIdx.x * 4;
    if (i < n) {
        float4 v = *reinterpret_cast<const float4*>(in + i);
        v.x = tf32f(v.x); v.y = tf32f(v.y); v.z = tf32f(v.z); v.w = tf32f(v.w);
        *reinterpret_cast<float4*>(out + i) = v;
    }
}

// ---------------- transpose + tf32 round ----------------
// out[e][c][r] = tf32(in[e][r][c]); R, C multiples of 32
__global__ void __launch_bounds__(256)
transpose_cvt(const float* __restrict__ in, float* __restrict__ out, int R, int C)
{
    __shared__ float tile[32][33];
    const int e = blockIdx.z;
    in  += (size_t)e * R * C;
    out += (size_t)e * R * C;
    const int c0 = blockIdx.x * 32;
    const int r0 = blockIdx.y * 32;
    #pragma unroll
    for (int i = threadIdx.y; i < 32; i += 8)
        tile[i][threadIdx.x] = in[(size_t)(r0 + i) * C + c0 + threadIdx.x];
    __syncthreads();
    #pragma unroll
    for (int i = threadIdx.y; i < 32; i += 8)
        out[(size_t)(c0 + i) * R + r0 + threadIdx.x] = tf32f(tile[threadIdx.x][i]);
}

// ---------------- pipelined tf32 mma.sync GEMM ----------------
// D[M,N] = act(A[M,K] @ BT[N,K]^T) per expert (blockIdx.z).
// A: [e][M][K], BT: [e][N][K], both row-major K-contiguous, tf32-pre-rounded.
template <bool GELU>
__global__ void __launch_bounds__(NTHREADS, 1)
gemm_tf32(const float* __restrict__ A, const float* __restrict__ BT,
          float* __restrict__ D, int M, int N, int K)
{
    extern __shared__ char smem[];
    const uint32_t sb = smem_u32(smem);

    const int e = blockIdx.z;
    A  += (size_t)e * M * K;
    BT += (size_t)e * N * K;
    D  += (size_t)e * M * N;

    const int tid  = threadIdx.x;
    const int lane = tid & 31;
    const int warp = tid >> 5;
    const int m0 = blockIdx.y * BM;
    const int n0 = blockIdx.x * BN;

    // 8 warps: 2 along M (64 rows), 4 along N (64 cols)
    const int wm = (warp & 1) * 64;
    const int wn = (warp >> 1) * 64;
    const int q = lane & 3;   // k sub-index
    const int r = lane >> 2;  // row/col sub-index

    const int nch = K / BK;

    // cp.async staging: op o covers smem row o>>3, 16B-quad o&7
    // A: 1024 ops (4/thread), B: 2048 ops (8/thread)
    auto load_stage = [&](int t) {
        const uint32_t base = sb + (uint32_t)(t % NSTAGES) * STAGE_BYTES;
        const int k0 = t * BK;
        #pragma unroll
        for (int i = 0; i < 4; ++i) {
            const int o = tid + 256 * i;
            const int row = o >> 3, q4 = o & 7;
            cp_async16(base + row * 144 + q4 * 16,
                       A + (size_t)(m0 + row) * K + k0 + q4 * 4);
        }
        const uint32_t bbase = base + A_STAGE_BYTES;
        #pragma unroll
        for (int i = 0; i < 8; ++i) {
            const int o = tid + 256 * i;
            const int row = o >> 3, q4 = o & 7;
            cp_async16(bbase + row * 144 + q4 * 16,
                       BT + (size_t)(n0 + row) * K + k0 + q4 * 4);
        }
    };

    float acc[4][8][4];
    #pragma unroll
    for (int i = 0; i < 4; i++)
        #pragma unroll
        for (int j = 0; j < 8; j++) {
            acc[i][j][0] = 0.f; acc[i][j][1] = 0.f;
            acc[i][j][2] = 0.f; acc[i][j][3] = 0.f;
        }

    load_stage(0); cp_commit();
    load_stage(1); cp_commit();

    #pragma unroll 1
    for (int t = 0; t < nch; ++t) {
        cp_wait1();          // stage t landed (this thread's groups)
        __syncthreads();     // ...and visible to all; prior compute drained

        if (t + 2 < nch) load_stage(t + 2);
        cp_commit();         // empty group ok — keeps group numbering aligned

        const float* As = reinterpret_cast<const float*>(
            smem + (size_t)(t % NSTAGES) * STAGE_BYTES);
        const float* Bs = reinterpret_cast<const float*>(
            smem + (size_t)(t % NSTAGES) * STAGE_BYTES + A_STAGE_BYTES);

        #pragma unroll
        for (int kk = 0; kk < 4; ++kk) {
            const int kb = kk * 8;

            unsigned af[4][4];
            #pragma unroll
            for (int mf = 0; mf < 4; mf++) {
                const int mr = wm + mf * 16 + r;
                af[mf][0] = __float_as_uint(As[mr * ROWF + kb + q]);
                af[mf][1] = __float_as_uint(As[(mr + 8) * ROWF + kb + q]);
                af[mf][2] = __float_as_uint(As[mr * ROWF + kb + q + 4]);
                af[mf][3] = __float_as_uint(As[(mr + 8) * ROWF + kb + q + 4]);
            }
            unsigned bf[8][2];
            #pragma unroll
            for (int nf = 0; nf < 8; nf++) {
                const int nc = wn + nf * 8 + r;
                bf[nf][0] = __float_as_uint(Bs[nc * ROWF + kb + q]);
                bf[nf][1] = __float_as_uint(Bs[nc * ROWF + kb + q + 4]);
            }

            #pragma unroll
            for (int mf = 0; mf < 4; mf++)
                #pragma unroll
                for (int nf = 0; nf < 8; nf++) {
                    asm volatile(
                        "mma.sync.aligned.m16n8k8.row.col.f32.tf32.tf32.f32 "
                        "{%0,%1,%2,%3}, {%4,%5,%6,%7}, {%8,%9}, {%0,%1,%2,%3};\n"
                        : "+f"(acc[mf][nf][0]), "+f"(acc[mf][nf][1]),
                          "+f"(acc[mf][nf][2]), "+f"(acc[mf][nf][3])
                        : "r"(af[mf][0]), "r"(af[mf][1]),
                          "r"(af[mf][2]), "r"(af[mf][3]),
                          "r"(bf[nf][0]), "r"(bf[nf][1]));
                }
        }
    }

    // Epilogue (accumulators in registers; GELU + tf32-round for GEMM1)
    #pragma unroll
    for (int mf = 0; mf < 4; mf++) {
        #pragma unroll
        for (int nf = 0; nf < 8; nf++) {
            const int row = m0 + wm + mf * 16 + r;
            const int col = n0 + wn + nf * 8 + 2 * q;
            float v0 = acc[mf][nf][0];
            float v1 = acc[mf][nf][1];
            float v2 = acc[mf][nf][2];
            float v3 = acc[mf][nf][3];
            if (GELU) {
                v0 = tf32f(gelu_exact(v0)); v1 = tf32f(gelu_exact(v1));
                v2 = tf32f(gelu_exact(v2)); v3 = tf32f(gelu_exact(v3));
            }
            *reinterpret_cast<float2*>(&D[(size_t)row * N + col]) = make_float2(v0, v1);
            *reinterpret_cast<float2*>(&D[(size_t)(row + 8) * N + col]) = make_float2(v2, v3);
        }
    }
}

// ---------------- launch ----------------
extern "C" void kernel_launch(void* const* d_in, const int* in_sizes, int n_in,
                              void* d_out, int out_size) {
    (void)in_sizes; (void)n_in; (void)out_size;
    const float* x  = (const float*)d_in[0];  // [E][C][H]
    const float* wi = (const float*)d_in[1];  // [E][H][I]
    const float* wo = (const float*)d_in[2];  // [E][I][H]
    float* out = (float*)d_out;               // [E][C][H]

    float *hidden, *xr, *wiT, *woT;
    cudaGetSymbolAddress((void**)&hidden, g_hidden);
    cudaGetSymbolAddress((void**)&xr, g_xr);
    cudaGetSymbolAddress((void**)&wiT, g_wiT);
    cudaGetSymbolAddress((void**)&woT, g_woT);

    cudaFuncSetAttribute(gemm_tf32<true>,
                         cudaFuncAttributeMaxDynamicSharedMemorySize, SMEM_TOTAL);
    cudaFuncSetAttribute(gemm_tf32<false>,
                         cudaFuncAttributeMaxDynamicSharedMemorySize, SMEM_TOTAL);

    // Pre-round / pre-transpose so the GEMM mainloop copies raw bits
    const size_t nx = (size_t)EXPERTS * CDIM * HDIM;
    round_tf32<<<(unsigned)(nx / 1024), 256>>>(x, xr, nx);
    transpose_cvt<<<dim3(IDIM / 32, HDIM / 32, EXPERTS), dim3(32, 8)>>>(wi, wiT, HDIM, IDIM);
    transpose_cvt<<<dim3(HDIM / 32, IDIM / 32, EXPERTS), dim3(32, 8)>>>(wo, woT, IDIM, HDIM);

    // GEMM1 + GELU: hidden[C,I] = gelu(xr[C,H] @ wiT[I,H]^T)
    gemm_tf32<true><<<dim3(IDIM / BN, CDIM / BM, EXPERTS), NTHREADS, SMEM_TOTAL>>>(
        xr, wiT, hidden, CDIM, IDIM, HDIM);
    // GEMM2: out[C,H] = hidden[C,I] @ woT[H,I]^T
    gemm_tf32<false><<<dim3(HDIM / BN, CDIM / BM, EXPERTS), NTHREADS, SMEM_TOTAL>>>(
        hidden, woT, out, CDIM, HDIM, IDIM);
}

// round 6
// speedup vs baseline: 1.4174x; 1.0443x over previous
#include <cuda_runtime.h>
#include <math.h>
#include <stdint.h>

// Problem: G=1, E=8, C=2048, H=1024, I=4096
#define EXPERTS 8
#define CDIM 2048
#define HDIM 1024
#define IDIM 4096

#define BM 128
#define BN 128
#define BK 32
#define NTHREADS 256
#define NSTAGES 3

// smem rows padded to 36 floats (144B): fragment bank = 4r+q, conflict-free
#define ROWF 36
#define A_STAGE_BYTES (BM * ROWF * 4)                  // 18432
#define B_STAGE_BYTES (BN * ROWF * 4)                  // 18432
#define STAGE_BYTES   (A_STAGE_BYTES + B_STAGE_BYTES)  // 36864
#define SMEM_TOTAL    (NSTAGES * STAGE_BYTES)          // 110592 -> 2 CTAs/SM

// Scratch (device globals; allocation APIs forbidden)
__device__ float g_hidden[(size_t)EXPERTS * CDIM * IDIM];  // 256 MB
__device__ float g_xr[(size_t)EXPERTS * CDIM * HDIM];      // 64 MB (tf32-rounded x)
__device__ float g_wiT[(size_t)EXPERTS * HDIM * IDIM];     // 128 MB [E][I][H]
__device__ float g_woT[(size_t)EXPERTS * HDIM * IDIM];     // 128 MB [E][H][I]

__device__ __forceinline__ float tf32f(float x) {
    float y;
    asm("cvt.rna.tf32.f32 %0, %1;" : "=f"(y) : "f"(x));
    return y;
}
__device__ __forceinline__ float gelu_exact(float x) {
    return 0.5f * x * (1.0f + erff(x * 0.70710678118654752440f));
}
__device__ __forceinline__ uint32_t smem_u32(const void* p) {
    uint32_t a;
    asm("{ .reg .u64 t; cvta.to.shared.u64 t, %1; cvt.u32.u64 %0, t; }" : "=r"(a) : "l"(p));
    return a;
}
__device__ __forceinline__ void cp_async16(uint32_t dst, const void* src) {
    asm volatile("cp.async.cg.shared.global [%0], [%1], 16;"
                 :: "r"(dst), "l"(src) : "memory");
}
__device__ __forceinline__ void cp_commit() {
    asm volatile("cp.async.commit_group;" ::: "memory");
}
__device__ __forceinline__ void cp_wait1() {
    asm volatile("cp.async.wait_group 1;" ::: "memory");
}

// ---------------- elementwise tf32 round ----------------
__global__ void __launch_bounds__(256)
round_tf32(const float* __restrict__ in, float* __restrict__ out, size_t n)
{
    size_t i = (size_t)blockIdx.x * 1024 + threadIdx.x * 4;
    if (i < n) {
        float4 v = *reinterpret_cast<const float4*>(in + i);
        v.x = tf32f(v.x); v.y = tf32f(v.y); v.z = tf32f(v.z); v.w = tf32f(v.w);
        *reinterpret_cast<float4*>(out + i) = v;
    }
}

// ---------------- transpose + tf32 round ----------------
// out[e][c][r] = tf32(in[e][r][c]); R, C multiples of 32
__global__ void __launch_bounds__(256)
transpose_cvt(const float* __restrict__ in, float* __restrict__ out, int R, int C)
{
    __shared__ float tile[32][33];
    const int e = blockIdx.z;
    in  += (size_t)e * R * C;
    out += (size_t)e * R * C;
    const int c0 = blockIdx.x * 32;
    const int r0 = blockIdx.y * 32;
    #pragma unroll
    for (int i = threadIdx.y; i < 32; i += 8)
        tile[i][threadIdx.x] = in[(size_t)(r0 + i) * C + c0 + threadIdx.x];
    __syncthreads();
    #pragma unroll
    for (int i = threadIdx.y; i < 32; i += 8)
        out[(size_t)(c0 + i) * R + r0 + threadIdx.x] = tf32f(tile[threadIdx.x][i]);
}

// ---------------- pipelined tf32 mma.sync GEMM ----------------
// D[M,N] = act(A[M,K] @ BT[N,K]^T) per expert (blockIdx.z).
// A: [e][M][K], BT: [e][N][K], both row-major K-contiguous, tf32-pre-rounded.
template <bool GELU>
__global__ void __launch_bounds__(NTHREADS, 2)
gemm_tf32(const float* __restrict__ A, const float* __restrict__ BT,
          float* __restrict__ D, int M, int N, int K)
{
    extern __shared__ char smem[];
    const uint32_t sb = smem_u32(smem);

    const int e = blockIdx.z;
    A  += (size_t)e * M * K;
    BT += (size_t)e * N * K;
    D  += (size_t)e * M * N;

    const int tid  = threadIdx.x;
    const int lane = tid & 31;
    const int warp = tid >> 5;
    const int m0 = blockIdx.y * BM;
    const int n0 = blockIdx.x * BN;

    // 8 warps: 2 along M (64 rows), 4 along N (32 cols) -> warp tile 64x32
    const int wm = (warp & 1) * 64;
    const int wn = (warp >> 1) * 32;
    const int q = lane & 3;   // k sub-index
    const int r = lane >> 2;  // row/col sub-index

    const int nch = K / BK;

    // cp.async staging: op o covers smem row o>>3, 16B-quad o&7.
    // A: 1024 ops (4/thread), B: 1024 ops (4/thread)
    auto load_stage = [&](int t) {
        const uint32_t base = sb + (uint32_t)(t % NSTAGES) * STAGE_BYTES;
        const int k0 = t * BK;
        #pragma unroll
        for (int i = 0; i < 4; ++i) {
            const int o = tid + 256 * i;
            const int row = o >> 3, q4 = o & 7;
            cp_async16(base + row * 144 + q4 * 16,
                       A + (size_t)(m0 + row) * K + k0 + q4 * 4);
        }
        const uint32_t bbase = base + A_STAGE_BYTES;
        #pragma unroll
        for (int i = 0; i < 4; ++i) {
            const int o = tid + 256 * i;
            const int row = o >> 3, q4 = o & 7;
            cp_async16(bbase + row * 144 + q4 * 16,
                       BT + (size_t)(n0 + row) * K + k0 + q4 * 4);
        }
    };

    float acc[4][4][4];
    #pragma unroll
    for (int i = 0; i < 4; i++)
        #pragma unroll
        for (int j = 0; j < 4; j++) {
            acc[i][j][0] = 0.f; acc[i][j][1] = 0.f;
            acc[i][j][2] = 0.f; acc[i][j][3] = 0.f;
        }

    load_stage(0); cp_commit();
    load_stage(1); cp_commit();

    #pragma unroll 1
    for (int t = 0; t < nch; ++t) {
        cp_wait1();          // stage t landed
        __syncthreads();     // visible to all; stage (t+2)%3 buffer is free

        if (t + 2 < nch) load_stage(t + 2);
        cp_commit();         // empty group ok — keeps group numbering aligned

        const float* As = reinterpret_cast<const float*>(
            smem + (size_t)(t % NSTAGES) * STAGE_BYTES);
        const float* Bs = reinterpret_cast<const float*>(
            smem + (size_t)(t % NSTAGES) * STAGE_BYTES + A_STAGE_BYTES);

        #pragma unroll
        for (int kk = 0; kk < 4; ++kk) {
            const int kb = kk * 8;

            unsigned af[4][4];
            #pragma unroll
            for (int mf = 0; mf < 4; mf++) {
                const int mr = wm + mf * 16 + r;
                af[mf][0] = __float_as_uint(As[mr * ROWF + kb + q]);
                af[mf][1] = __float_as_uint(As[(mr + 8) * ROWF + kb + q]);
                af[mf][2] = __float_as_uint(As[mr * ROWF + kb + q + 4]);
                af[mf][3] = __float_as_uint(As[(mr + 8) * ROWF + kb + q + 4]);
            }
            unsigned bf[4][2];
            #pragma unroll
            for (int nf = 0; nf < 4; nf++) {
                const int nc = wn + nf * 8 + r;
                bf[nf][0] = __float_as_uint(Bs[nc * ROWF + kb + q]);
                bf[nf][1] = __float_as_uint(Bs[nc * ROWF + kb + q + 4]);
            }

            #pragma unroll
            for (int mf = 0; mf < 4; mf++)
                #pragma unroll
                for (int nf = 0; nf < 4; nf++) {
                    asm volatile(
                        "mma.sync.aligned.m16n8k8.row.col.f32.tf32.tf32.f32 "
                        "{%0,%1,%2,%3}, {%4,%5,%6,%7}, {%8,%9}, {%0,%1,%2,%3};\n"
                        : "+f"(acc[mf][nf][0]), "+f"(acc[mf][nf][1]),
                          "+f"(acc[mf][nf][2]), "+f"(acc[mf][nf][3])
                        : "r"(af[mf][0]), "r"(af[mf][1]),
                          "r"(af[mf][2]), "r"(af[mf][3]),
                          "r"(bf[nf][0]), "r"(bf[nf][1]));
                }
        }
    }

    // Epilogue (accumulators in registers; GELU + tf32-round for GEMM1)
    #pragma unroll
    for (int mf = 0; mf < 4; mf++) {
        #pragma unroll
        for (int nf = 0; nf < 4; nf++) {
            const int row = m0 + wm + mf * 16 + r;
            const int col = n0 + wn + nf * 8 + 2 * q;
            float v0 = acc[mf][nf][0];
            float v1 = acc[mf][nf][1];
            float v2 = acc[mf][nf][2];
            float v3 = acc[mf][nf][3];
            if (GELU) {
                v0 = tf32f(gelu_exact(v0)); v1 = tf32f(gelu_exact(v1));
                v2 = tf32f(gelu_exact(v2)); v3 = tf32f(gelu_exact(v3));
            }
            *reinterpret_cast<float2*>(&D[(size_t)row * N + col]) = make_float2(v0, v1);
            *reinterpret_cast<float2*>(&D[(size_t)(row + 8) * N + col]) = make_float2(v2, v3);
        }
    }
}

// ---------------- launch ----------------
extern "C" void kernel_launch(void* const* d_in, const int* in_sizes, int n_in,
                              void* d_out, int out_size) {
    (void)in_sizes; (void)n_in; (void)out_size;
    const float* x  = (const float*)d_in[0];  // [E][C][H]
    const float* wi = (const float*)d_in[1];  // [E][H][I]
    const float* wo = (const float*)d_in[2];  // [E][I][H]
    float* out = (float*)d_out;               // [E][C][H]

    float *hidden, *xr, *wiT, *woT;
    cudaGetSymbolAddress((void**)&hidden, g_hidden);
    cudaGetSymbolAddress((void**)&xr, g_xr);
    cudaGetSymbolAddress((void**)&wiT, g_wiT);
    cudaGetSymbolAddress((void**)&woT, g_woT);

    cudaFuncSetAttribute(gemm_tf32<true>,
                         cudaFuncAttributeMaxDynamicSharedMemorySize, SMEM_TOTAL);
    cudaFuncSetAttribute(gemm_tf32<false>,
                         cudaFuncAttributeMaxDynamicSharedMemorySize, SMEM_TOTAL);

    // Pre-round / pre-transpose so the GEMM mainloop copies raw bits
    const size_t nx = (size_t)EXPERTS * CDIM * HDIM;
    round_tf32<<<(unsigned)(nx / 1024), 256>>>(x, xr, nx);
    transpose_cvt<<<dim3(IDIM / 32, HDIM / 32, EXPERTS), dim3(32, 8)>>>(wi, wiT, HDIM, IDIM);
    transpose_cvt<<<dim3(HDIM / 32, IDIM / 32, EXPERTS), dim3(32, 8)>>>(wo, woT, IDIM, HDIM);

    // GEMM1 + GELU: hidden[C,I] = gelu(xr[C,H] @ wiT[I,H]^T)
    gemm_tf32<true><<<dim3(IDIM / BN, CDIM / BM, EXPERTS), NTHREADS, SMEM_TOTAL>>>(
        xr, wiT, hidden, CDIM, IDIM, HDIM);
    // GEMM2: out[C,H] = hidden[C,I] @ woT[H,I]^T
    gemm_tf32<false><<<dim3(HDIM / BN, CDIM / BM, EXPERTS), NTHREADS, SMEM_TOTAL>>>(
        hidden, woT, out, CDIM, HDIM, IDIM);
}

// round 7
// speedup vs baseline: 1.5994x; 1.1285x over previous
#include <cuda_runtime.h>
#include <math.h>
#include <stdint.h>

// Problem: G=1, E=8, C=2048, H=1024, I=4096
#define EXPERTS 8
#define CDIM 2048
#define HDIM 1024
#define IDIM 4096

#define BM 128
#define BN 128
#define BK 32
#define NTHREADS 256
#define NSTAGES 3

// Rows are 32 floats (128B) with XOR swizzle on 8B pairs: p' = p ^ ((row&3)<<2)
#define A_STAGE_BYTES (BM * 128)                       // 16384
#define B_STAGE_BYTES (BN * 128)                       // 16384
#define STAGE_BYTES   (A_STAGE_BYTES + B_STAGE_BYTES)  // 32768
#define SMEM_TOTAL    (NSTAGES * STAGE_BYTES)          // 98304 -> 2 CTAs/SM

// K dimension is pre-permuted in groups of 8: order [0,4,1,5,2,6,3,7]
// perm(s) = s<4 ? 2s : 2(s-4)+1 ; pairs (k, k+4) land on adjacent floats.

// Scratch (device globals; allocation APIs forbidden)
__device__ float g_hidden[(size_t)EXPERTS * CDIM * IDIM];  // 256 MB (K-permuted)
__device__ float g_xr[(size_t)EXPERTS * CDIM * HDIM];      // 64 MB  (K-permuted)
__device__ float g_wiT[(size_t)EXPERTS * HDIM * IDIM];     // 128 MB [E][I][H] (K-permuted)
__device__ float g_woT[(size_t)EXPERTS * HDIM * IDIM];     // 128 MB [E][H][I] (K-permuted)

__device__ __forceinline__ float tf32f(float x) {
    float y;
    asm("cvt.rna.tf32.f32 %0, %1;" : "=f"(y) : "f"(x));
    return y;
}
__device__ __forceinline__ float gelu_exact(float x) {
    return 0.5f * x * (1.0f + erff(x * 0.70710678118654752440f));
}
__device__ __forceinline__ uint32_t smem_u32(const void* p) {
    uint32_t a;
    asm("{ .reg .u64 t; cvta.to.shared.u64 t, %1; cvt.u32.u64 %0, t; }" : "=r"(a) : "l"(p));
    return a;
}
__device__ __forceinline__ void cp_async16(uint32_t dst, const void* src) {
    asm volatile("cp.async.cg.shared.global [%0], [%1], 16;"
                 :: "r"(dst), "l"(src) : "memory");
}
__device__ __forceinline__ void cp_commit() {
    asm volatile("cp.async.commit_group;" ::: "memory");
}
__device__ __forceinline__ void cp_wait1() {
    asm volatile("cp.async.wait_group 1;" ::: "memory");
}

// ---------------- tf32 round + K-permute (groups of 8) ----------------
// Each thread handles one 8-group: out[8j+perm(s)] = tf32(in[8j+s])
__global__ void __launch_bounds__(256)
round_perm_tf32(const float* __restrict__ in, float* __restrict__ out, size_t n8)
{
    size_t j = (size_t)blockIdx.x * 256 + threadIdx.x;
    if (j >= n8) return;
    const float4* ip = reinterpret_cast<const float4*>(in + 8 * j);
    float4 lo = ip[0], hi = ip[1];   // lo = k0..3, hi = k4..7
    float4 o0, o1;
    o0.x = tf32f(lo.x); o0.y = tf32f(hi.x); o0.z = tf32f(lo.y); o0.w = tf32f(hi.y);
    o1.x = tf32f(lo.z); o1.y = tf32f(hi.z); o1.z = tf32f(lo.w); o1.w = tf32f(hi.w);
    float4* op = reinterpret_cast<float4*>(out + 8 * j);
    op[0] = o0; op[1] = o1;
}

// ---------------- transpose + tf32 round + K-permute on output minor dim ----
// out[e][c][r'] = tf32(in[e][r][c]) with r' permuted within 8-groups.
__global__ void __launch_bounds__(256)
transpose_cvt_perm(const float* __restrict__ in, float* __restrict__ out, int R, int C)
{
    __shared__ float tile[32][33];
    const int e = blockIdx.z;
    in  += (size_t)e * R * C;
    out += (size_t)e * R * C;
    const int c0 = blockIdx.x * 32;
    const int r0 = blockIdx.y * 32;
    const int tx = threadIdx.x;
    #pragma unroll
    for (int i = threadIdx.y; i < 32; i += 8)
        tile[i][tx] = in[(size_t)(r0 + i) * C + c0 + tx];
    __syncthreads();
    // position p gets source s = invperm(p): p odd -> (p>>1)+4, else p>>1
    const int p = tx & 7;
    const int src = (tx & ~7) | ((p & 1) ? ((p >> 1) + 4) : (p >> 1));
    #pragma unroll
    for (int i = threadIdx.y; i < 32; i += 8)
        out[(size_t)(c0 + i) * R + r0 + tx] = tf32f(tile[src][i]);
}

// ---------------- pipelined tf32 mma.sync GEMM (K-permuted inputs) ----------
// D[M,N] = act(A[M,K] @ BT[N,K]^T) per expert (blockIdx.z).
// A: [e][M][K], BT: [e][N][K], K-contiguous, tf32-rounded, K-permuted.
// If GELU: D written K-permuted along N (it feeds GEMM2 as A).
template <bool GELU>
__global__ void __launch_bounds__(NTHREADS, 2)
gemm_tf32(const float* __restrict__ A, const float* __restrict__ BT,
          float* __restrict__ D, int M, int N, int K)
{
    extern __shared__ char smem[];
    const uint32_t sb = smem_u32(smem);

    const int e = blockIdx.z;
    A  += (size_t)e * M * K;
    BT += (size_t)e * N * K;
    D  += (size_t)e * M * N;

    const int tid  = threadIdx.x;
    const int lane = tid & 31;
    const int warp = tid >> 5;
    const int m0 = blockIdx.y * BM;
    const int n0 = blockIdx.x * BN;

    // 8 warps: 2 along M (64 rows), 4 along N (32 cols)
    const int wm = (warp & 1) * 64;
    const int wn = (warp >> 1) * 32;
    const int q  = lane & 3;
    const int r  = lane >> 2;
    const int r3 = r & 3;

    const int nch = K / BK;

    // cp.async with pair-swizzle: quad q4 stored at q4 ^ ((row&3)<<1)
    auto load_stage = [&](int t) {
        const uint32_t base = sb + (uint32_t)(t % NSTAGES) * STAGE_BYTES;
        const int k0 = t * BK;
        #pragma unroll
        for (int i = 0; i < 4; ++i) {
            const int o = tid + 256 * i;
            const int row = o >> 3, q4 = o & 7;
            const int q4s = q4 ^ ((row & 3) << 1);
            cp_async16(base + row * 128 + q4s * 16,
                       A + (size_t)(m0 + row) * K + k0 + q4 * 4);
        }
        const uint32_t bbase = base + A_STAGE_BYTES;
        #pragma unroll
        for (int i = 0; i < 4; ++i) {
            const int o = tid + 256 * i;
            const int row = o >> 3, q4 = o & 7;
            const int q4s = q4 ^ ((row & 3) << 1);
            cp_async16(bbase + row * 128 + q4s * 16,
                       BT + (size_t)(n0 + row) * K + k0 + q4 * 4);
        }
    };

    // Precomputed row byte-offsets within a stage
    uint32_t aoff[4][2];
    #pragma unroll
    for (int mf = 0; mf < 4; ++mf) {
        const int mr = wm + mf * 16 + r;
        aoff[mf][0] = (uint32_t)(mr * 128);
        aoff[mf][1] = (uint32_t)((mr + 8) * 128);
    }
    uint32_t boff[4];
    #pragma unroll
    for (int nf = 0; nf < 4; ++nf)
        boff[nf] = (uint32_t)((wn + nf * 8 + r) * 128);

    float acc[4][4][4];
    #pragma unroll
    for (int i = 0; i < 4; i++)
        #pragma unroll
        for (int j = 0; j < 4; j++) {
            acc[i][j][0] = 0.f; acc[i][j][1] = 0.f;
            acc[i][j][2] = 0.f; acc[i][j][3] = 0.f;
        }

    load_stage(0); cp_commit();
    load_stage(1); cp_commit();

    #pragma unroll 1
    for (int t = 0; t < nch; ++t) {
        cp_wait1();
        __syncthreads();

        if (t + 2 < nch) load_stage(t + 2);
        cp_commit();   // empty group ok — keeps numbering aligned

        const char* Asb = smem + (size_t)(t % NSTAGES) * STAGE_BYTES;
        const char* Bsb = Asb + A_STAGE_BYTES;

        #pragma unroll
        for (int kk = 0; kk < 4; ++kk) {
            // pair index p = kk*4 + q, swizzled by row (&3)==r3, 8 bytes each
            const uint32_t pb = (uint32_t)((((kk << 2) | q) ^ (r3 << 2)) << 3);

            float2 afl[4], afh[4];   // afl: row mr (k=q lo, k=q+4 hi); afh: row mr+8
            #pragma unroll
            for (int mf = 0; mf < 4; mf++) {
                afl[mf] = *reinterpret_cast<const float2*>(Asb + aoff[mf][0] + pb);
                afh[mf] = *reinterpret_cast<const float2*>(Asb + aoff[mf][1] + pb);
            }
            float2 bfp[4];
            #pragma unroll
            for (int nf = 0; nf < 4; nf++)
                bfp[nf] = *reinterpret_cast<const float2*>(Bsb + boff[nf] + pb);

            #pragma unroll
            for (int mf = 0; mf < 4; mf++)
                #pragma unroll
                for (int nf = 0; nf < 4; nf++) {
                    asm volatile(
                        "mma.sync.aligned.m16n8k8.row.col.f32.tf32.tf32.f32 "
                        "{%0,%1,%2,%3}, {%4,%5,%6,%7}, {%8,%9}, {%0,%1,%2,%3};\n"
                        : "+f"(acc[mf][nf][0]), "+f"(acc[mf][nf][1]),
                          "+f"(acc[mf][nf][2]), "+f"(acc[mf][nf][3])
                        : "r"(__float_as_uint(afl[mf].x)), "r"(__float_as_uint(afh[mf].x)),
                          "r"(__float_as_uint(afl[mf].y)), "r"(__float_as_uint(afh[mf].y)),
                          "r"(__float_as_uint(bfp[nf].x)), "r"(__float_as_uint(bfp[nf].y)));
                }
        }
    }

    // Epilogue
    #pragma unroll
    for (int mf = 0; mf < 4; mf++) {
        #pragma unroll
        for (int nf = 0; nf < 4; nf++) {
            const int row = m0 + wm + mf * 16 + r;
            const int nb  = n0 + wn + nf * 8;
            float v0 = acc[mf][nf][0];
            float v1 = acc[mf][nf][1];
            float v2 = acc[mf][nf][2];
            float v3 = acc[mf][nf][3];
            if (GELU) {
                // gelu + tf32-round, then write K-PERMUTED along N for GEMM2
                v0 = tf32f(gelu_exact(v0)); v1 = tf32f(gelu_exact(v1));
                v2 = tf32f(gelu_exact(v2)); v3 = tf32f(gelu_exact(v3));
                const int s0 = 2 * q, s1 = 2 * q + 1;
                const int p0 = (s0 < 4) ? 2 * s0 : 2 * (s0 - 4) + 1;
                const int p1 = (s1 < 4) ? 2 * s1 : 2 * (s1 - 4) + 1;
                D[(size_t)row * N + nb + p0] = v0;
                D[(size_t)row * N + nb + p1] = v1;
                D[(size_t)(row + 8) * N + nb + p0] = v2;
                D[(size_t)(row + 8) * N + nb + p1] = v3;
            } else {
                const int col = nb + 2 * q;
                *reinterpret_cast<float2*>(&D[(size_t)row * N + col]) = make_float2(v0, v1);
                *reinterpret_cast<float2*>(&D[(size_t)(row + 8) * N + col]) = make_float2(v2, v3);
            }
        }
    }
}

// ---------------- launch ----------------
extern "C" void kernel_launch(void* const* d_in, const int* in_sizes, int n_in,
                              void* d_out, int out_size) {
    (void)in_sizes; (void)n_in; (void)out_size;
    const float* x  = (const float*)d_in[0];  // [E][C][H]
    const float* wi = (const float*)d_in[1];  // [E][H][I]
    const float* wo = (const float*)d_in[2];  // [E][I][H]
    float* out = (float*)d_out;               // [E][C][H]

    float *hidden, *xr, *wiT, *woT;
    cudaGetSymbolAddress((void**)&hidden, g_hidden);
    cudaGetSymbolAddress((void**)&xr, g_xr);
    cudaGetSymbolAddress((void**)&wiT, g_wiT);
    cudaGetSymbolAddress((void**)&woT, g_woT);

    cudaFuncSetAttribute(gemm_tf32<true>,
                         cudaFuncAttributeMaxDynamicSharedMemorySize, SMEM_TOTAL);
    cudaFuncSetAttribute(gemm_tf32<false>,
                         cudaFuncAttributeMaxDynamicSharedMemorySize, SMEM_TOTAL);

    // Pre-round + K-permute x; pre-transpose + round + permute weights
    const size_t n8 = (size_t)EXPERTS * CDIM * HDIM / 8;
    round_perm_tf32<<<(unsigned)((n8 + 255) / 256), 256>>>(x, xr, n8);
    transpose_cvt_perm<<<dim3(IDIM / 32, HDIM / 32, EXPERTS), dim3(32, 8)>>>(wi, wiT, HDIM, IDIM);
    transpose_cvt_perm<<<dim3(HDIM / 32, IDIM / 32, EXPERTS), dim3(32, 8)>>>(wo, woT, IDIM, HDIM);

    // GEMM1 + GELU: hidden[C,I] = gelu(xr[C,H] @ wiT[I,H]^T)   (hidden K-permuted)
    gemm_tf32<true><<<dim3(IDIM / BN, CDIM / BM, EXPERTS), NTHREADS, SMEM_TOTAL>>>(
        xr, wiT, hidden, CDIM, IDIM, HDIM);
    // GEMM2: out[C,H] = hidden[C,I] @ woT[H,I]^T
    gemm_tf32<false><<<dim3(HDIM / BN, CDIM / BM, EXPERTS), NTHREADS, SMEM_TOTAL>>>(
        hidden, woT, out, CDIM, HDIM, IDIM);
}

// round 9
// speedup vs baseline: 1.7246x; 1.0782x over previous
#include <cuda_runtime.h>
#include <math.h>
#include <stdint.h>

// Problem: G=1, E=8, C=2048, H=1024, I=4096
#define EXPERTS 8
#define CDIM 2048
#define HDIM 1024
#define IDIM 4096

#define BM 128
#define BN 128
#define BK 32
#define NTHREADS 256
#define NSTAGES 3

// Rows are 32 floats (128B); 8B pairs XOR-swizzled: p' = p ^ ((row&3)<<2)
#define A_STAGE_BYTES (BM * 128)                       // 16384
#define B_STAGE_BYTES (BN * 128)                       // 16384
#define STAGE_BYTES   (A_STAGE_BYTES + B_STAGE_BYTES)  // 32768
#define SMEM_TOTAL    (NSTAGES * STAGE_BYTES)          // 98304 -> 2 CTAs/SM

// K dimension pre-permuted in groups of 8: order [0,4,1,5,2,6,3,7]
// perm(s) = s<4 ? 2s : 2(s-4)+1 ; pairs (k, k+4) are adjacent floats.

// Scratch (device globals; allocation APIs forbidden)
__device__ float g_hidden[(size_t)EXPERTS * CDIM * IDIM];  // 256 MB (K-permuted)
__device__ float g_xr[(size_t)EXPERTS * CDIM * HDIM];      // 64 MB  (K-permuted)
__device__ float g_wiT[(size_t)EXPERTS * HDIM * IDIM];     // 128 MB [E][I][H] (K-permuted)
__device__ float g_woT[(size_t)EXPERTS * HDIM * IDIM];     // 128 MB [E][H][I] (K-permuted)

__device__ __forceinline__ float tf32f(float x) {
    float y;
    asm("cvt.rna.tf32.f32 %0, %1;" : "=f"(y) : "f"(x));
    return y;
}
__device__ __forceinline__ float gelu_exact(float x) {
    return 0.5f * x * (1.0f + erff(x * 0.70710678118654752440f));
}
__device__ __forceinline__ uint32_t smem_u32(const void* p) {
    uint32_t a;
    asm("{ .reg .u64 t; cvta.to.shared.u64 t, %1; cvt.u32.u64 %0, t; }" : "=r"(a) : "l"(p));
    return a;
}
__device__ __forceinline__ void cp_async16(uint32_t dst, const void* src) {
    asm volatile("cp.async.cg.shared.global [%0], [%1], 16;"
                 :: "r"(dst), "l"(src) : "memory");
}
__device__ __forceinline__ void cp_commit() {
    asm volatile("cp.async.commit_group;" ::: "memory");
}
__device__ __forceinline__ void cp_wait1() {
    asm volatile("cp.async.wait_group 1;" ::: "memory");
}

// ---------------- tf32 round + K-permute (groups of 8) ----------------
__global__ void __launch_bounds__(256)
round_perm_tf32(const float* __restrict__ in, float* __restrict__ out, size_t n8)
{
    size_t j = (size_t)blockIdx.x * 256 + threadIdx.x;
    if (j >= n8) return;
    const float4* ip = reinterpret_cast<const float4*>(in + 8 * j);
    float4 lo = ip[0], hi = ip[1];
    float4 o0, o1;
    o0.x = tf32f(lo.x); o0.y = tf32f(hi.x); o0.z = tf32f(lo.y); o0.w = tf32f(hi.y);
    o1.x = tf32f(lo.z); o1.y = tf32f(hi.z); o1.z = tf32f(lo.w); o1.w = tf32f(hi.w);
    float4* op = reinterpret_cast<float4*>(out + 8 * j);
    op[0] = o0; op[1] = o1;
}

// ---------------- transpose + tf32 round + K-permute on output minor dim ----
__global__ void __launch_bounds__(256)
transpose_cvt_perm(const float* __restrict__ in, float* __restrict__ out, int R, int C)
{
    __shared__ float tile[32][33];
    const int e = blockIdx.z;
    in  += (size_t)e * R * C;
    out += (size_t)e * R * C;
    const int c0 = blockIdx.x * 32;
    const int r0 = blockIdx.y * 32;
    const int tx = threadIdx.x;
    #pragma unroll
    for (int i = threadIdx.y; i < 32; i += 8)
        tile[i][tx] = in[(size_t)(r0 + i) * C + c0 + tx];
    __syncthreads();
    const int p = tx & 7;
    const int src = (tx & ~7) | ((p & 1) ? ((p >> 1) + 4) : (p >> 1));
    #pragma unroll
    for (int i = threadIdx.y; i < 32; i += 8)
        out[(size_t)(c0 + i) * R + r0 + tx] = tf32f(tile[src][i]);
}

// ---------------- pipelined tf32 mma.sync GEMM (K-permuted inputs) ----------
// D[M,N] = act(A[M,K] @ BT[N,K]^T) per expert (blockIdx.z).
// K, N compile-time so all strides fold into immediates.
template <bool GELU, int K, int N>
__global__ void __launch_bounds__(NTHREADS, 2)
gemm_tf32(const float* __restrict__ A, const float* __restrict__ BT,
          float* __restrict__ D)
{
    constexpr int M = CDIM;
    constexpr int nch = K / BK;

    extern __shared__ char smem[];
    const uint32_t sb = smem_u32(smem);

    const int e = blockIdx.z;
    A  += (size_t)e * M * K;
    BT += (size_t)e * N * K;
    D  += (size_t)e * M * N;

    const int tid  = threadIdx.x;
    const int lane = tid & 31;
    const int warp = tid >> 5;
    const int m0 = blockIdx.y * BM;
    const int n0 = blockIdx.x * BN;

    // 8 warps: 2 along M (64 rows), 4 along N (32 cols)
    const int wm = (warp & 1) * 64;
    const int wn = (warp >> 1) * 32;
    const int q  = lane & 3;
    const int r  = lane >> 2;
    const int r3 = r & 3;

    // --- loop-invariant addressing ---
    // cp.async: this thread covers rows r0+32i, quad q4 (const across i)
    const int r0g = tid >> 3;
    const int q4  = tid & 7;
    const int q4s = q4 ^ ((r0g & 3) << 1);
    const char* gA = reinterpret_cast<const char*>(A + (size_t)(m0 + r0g) * K) + q4 * 16;
    const char* gB = reinterpret_cast<const char*>(BT + (size_t)(n0 + r0g) * K) + q4 * 16;
    const uint32_t dstA0 = (uint32_t)(r0g * 128 + q4s * 16);
    const uint32_t dstB0 = dstA0 + A_STAGE_BYTES;

    // LDS: swizzled pair offsets per kk (loop-invariant registers)
    uint32_t pb[4];
    #pragma unroll
    for (int kk = 0; kk < 4; ++kk)
        pb[kk] = (uint32_t)(((((kk << 2) | q) ^ (r3 << 2))) << 3);
    const uint32_t arow = (uint32_t)((wm + r) * 128);
    const uint32_t brow = (uint32_t)((wn + r) * 128) + A_STAGE_BYTES;

    float acc[4][4][4];
    #pragma unroll
    for (int i = 0; i < 4; i++)
        #pragma unroll
        for (int j = 0; j < 4; j++) {
            acc[i][j][0] = 0.f; acc[i][j][1] = 0.f;
            acc[i][j][2] = 0.f; acc[i][j][3] = 0.f;
        }

    // prologue: stages 0 and 1
    #pragma unroll
    for (int s = 0; s < 2; ++s) {
        const uint32_t ab = sb + (uint32_t)s * STAGE_BYTES + dstA0;
        const uint32_t bb = sb + (uint32_t)s * STAGE_BYTES + dstB0;
        #pragma unroll
        for (int i = 0; i < 4; ++i)
            cp_async16(ab + i * 4096, gA + (size_t)i * (32 * K * 4));
        #pragma unroll
        for (int i = 0; i < 4; ++i)
            cp_async16(bb + i * 4096, gB + (size_t)i * (32 * K * 4));
        cp_commit();
        gA += BK * 4; gB += BK * 4;
    }

    uint32_t soff_c = 0;                       // stage offset being consumed
    uint32_t soff_p = 2 * STAGE_BYTES;         // stage offset being produced

    #pragma unroll 1
    for (int t = 0; t < nch; ++t) {
        cp_wait1();
        __syncthreads();

        if (t + 2 < nch) {
            const uint32_t ab = sb + soff_p + dstA0;
            const uint32_t bb = sb + soff_p + dstB0;
            #pragma unroll
            for (int i = 0; i < 4; ++i)
                cp_async16(ab + i * 4096, gA + (size_t)i * (32 * K * 4));
            #pragma unroll
            for (int i = 0; i < 4; ++i)
                cp_async16(bb + i * 4096, gB + (size_t)i * (32 * K * 4));
            gA += BK * 4; gB += BK * 4;
            soff_p = (soff_p == 2 * STAGE_BYTES) ? 0u : soff_p + STAGE_BYTES;
        }
        cp_commit();   // empty group ok — keeps numbering aligned

        const char* Ab = smem + soff_c + arow;
        const char* Bb = smem + soff_c + brow;
        soff_c = (soff_c == 2 * STAGE_BYTES) ? 0u : soff_c + STAGE_BYTES;

        #pragma unroll
        for (int kk = 0; kk < 4; ++kk) {
            const char* Ak = Ab + pb[kk];
            const char* Bk = Bb + pb[kk];

            float2 afl[4], afh[4], bfp[4];
            #pragma unroll
            for (int mf = 0; mf < 4; mf++) {
                afl[mf] = *reinterpret_cast<const float2*>(Ak + mf * 2048);
                afh[mf] = *reinterpret_cast<const float2*>(Ak + mf * 2048 + 1024);
            }
            #pragma unroll
            for (int nf = 0; nf < 4; nf++)
                bfp[nf] = *reinterpret_cast<const float2*>(Bk + nf * 1024);

            #pragma unroll
            for (int mf = 0; mf < 4; mf++)
                #pragma unroll
                for (int nf = 0; nf < 4; nf++) {
                    asm volatile(
                        "mma.sync.aligned.m16n8k8.row.col.f32.tf32.tf32.f32 "
                        "{%0,%1,%2,%3}, {%4,%5,%6,%7}, {%8,%9}, {%0,%1,%2,%3};\n"
                        : "+f"(acc[mf][nf][0]), "+f"(acc[mf][nf][1]),
                          "+f"(acc[mf][nf][2]), "+f"(acc[mf][nf][3])
                        : "r"(__float_as_uint(afl[mf].x)), "r"(__float_as_uint(afh[mf].x)),
                          "r"(__float_as_uint(afl[mf].y)), "r"(__float_as_uint(afh[mf].y)),
                          "r"(__float_as_uint(bfp[nf].x)), "r"(__float_as_uint(bfp[nf].y)));
                }
        }
    }

    // Epilogue
    #pragma unroll
    for (int mf = 0; mf < 4; mf++) {
        #pragma unroll
        for (int nf = 0; nf < 4; nf++) {
            const int row = m0 + wm + mf * 16 + r;
            const int nb  = n0 + wn + nf * 8;
            float v0 = acc[mf][nf][0];
            float v1 = acc[mf][nf][1];
            float v2 = acc[mf][nf][2];
            float v3 = acc[mf][nf][3];
            if (GELU) {
                // gelu + tf32-round, write K-PERMUTED along N for GEMM2
                v0 = tf32f(gelu_exact(v0)); v1 = tf32f(gelu_exact(v1));
                v2 = tf32f(gelu_exact(v2)); v3 = tf32f(gelu_exact(v3));
                const int s0 = 2 * q, s1 = 2 * q + 1;
                const int p0 = (s0 < 4) ? 2 * s0 : 2 * (s0 - 4) + 1;
                const int p1 = (s1 < 4) ? 2 * s1 : 2 * (s1 - 4) + 1;
                D[(size_t)row * N + nb + p0] = v0;
                D[(size_t)row * N + nb + p1] = v1;
                D[(size_t)(row + 8) * N + nb + p0] = v2;
                D[(size_t)(row + 8) * N + nb + p1] = v3;
            } else {
                const int col = nb + 2 * q;
                *reinterpret_cast<float2*>(&D[(size_t)row * N + col]) = make_float2(v0, v1);
                *reinterpret_cast<float2*>(&D[(size_t)(row + 8) * N + col]) = make_float2(v2, v3);
            }
        }
    }
}

// ---------------- launch ----------------
extern "C" void kernel_launch(void* const* d_in, const int* in_sizes, int n_in,
                              void* d_out, int out_size) {
    (void)in_sizes; (void)n_in; (void)out_size;
    const float* x  = (const float*)d_in[0];  // [E][C][H]
    const float* wi = (const float*)d_in[1];  // [E][H][I]
    const float* wo = (const float*)d_in[2];  // [E][I][H]
    float* out = (float*)d_out;               // [E][C][H]

    float *hidden, *xr, *wiT, *woT;
    cudaGetSymbolAddress((void**)&hidden, g_hidden);
    cudaGetSymbolAddress((void**)&xr, g_xr);
    cudaGetSymbolAddress((void**)&wiT, g_wiT);
    cudaGetSymbolAddress((void**)&woT, g_woT);

    cudaFuncSetAttribute((const void*)gemm_tf32<true, HDIM, IDIM>,
                         cudaFuncAttributeMaxDynamicSharedMemorySize, SMEM_TOTAL);
    cudaFuncSetAttribute((const void*)gemm_tf32<false, IDIM, HDIM>,
                         cudaFuncAttributeMaxDynamicSharedMemorySize, SMEM_TOTAL);

    // Pre-round + K-permute x; pre-transpose + round + permute weights
    const size_t n8 = (size_t)EXPERTS * CDIM * HDIM / 8;
    round_perm_tf32<<<(unsigned)((n8 + 255) / 256), 256>>>(x, xr, n8);
    transpose_cvt_perm<<<dim3(IDIM / 32, HDIM / 32, EXPERTS), dim3(32, 8)>>>(wi, wiT, HDIM, IDIM);
    transpose_cvt_perm<<<dim3(HDIM / 32, IDIM / 32, EXPERTS), dim3(32, 8)>>>(wo, woT, IDIM, HDIM);

    // GEMM1 + GELU: hidden[C,I] = gelu(xr[C,H] @ wiT[I,H]^T)   (hidden K-permuted)
    gemm_tf32<true, HDIM, IDIM><<<dim3(IDIM / BN, CDIM / BM, EXPERTS), NTHREADS, SMEM_TOTAL>>>(
        xr, wiT, hidden);
    // GEMM2: out[C,H] = hidden[C,I] @ woT[H,I]^T
    gemm_tf32<false, IDIM, HDIM><<<dim3(HDIM / BN, CDIM / BM, EXPERTS), NTHREADS, SMEM_TOTAL>>>(
        hidden, woT, out);
}